// round 5
// baseline (speedup 1.0000x reference)
#include <cuda_runtime.h>

#define Hh 128
#define Ww 128
#define Cc 64
#define PAD 3
#define HP 134
#define WP 134
#define WS 7
#define SST 160   // padded S row stride / smem Q,K width (even: aligned LDS.64)
#define HPWP (HP * WP)

// ---------------- f32x2 helpers (packed fp32 FMA, sm_100+) -----------------
__device__ __forceinline__ unsigned long long ffma2(unsigned long long a,
                                                    unsigned long long b,
                                                    unsigned long long c) {
    unsigned long long d;
    asm("fma.rn.f32x2 %0, %1, %2, %3;" : "=l"(d) : "l"(a), "l"(b), "l"(c));
    return d;
}
__device__ __forceinline__ unsigned long long pk2(float lo, float hi) {
    unsigned long long d;
    asm("mov.b64 %0, {%1, %2};" : "=l"(d) : "f"(lo), "f"(hi));
    return d;
}
__device__ __forceinline__ unsigned long long pkf2(float2 v) {
    return pk2(v.x, v.y);
}
__device__ __forceinline__ float2 upk(unsigned long long d) {
    float2 v;
    asm("mov.b64 {%0, %1}, %2;" : "=f"(v.x), "=f"(v.y) : "l"(d));
    return v;
}

// ---------------- scratch (device globals; no allocation allowed) ----------
__device__ float g_qpad[Cc * HPWP];      // padded q  (C, HP, WP)
__device__ float g_kpad[Cc * HPWP];
__device__ float g_vpad[Cc * HPWP];
__device__ float g_T[HP * Hh * Ww];      // T[r][w][k] = sum_pj S_r[w+pj, k+pj]
__device__ float g_attn[Hh * Ww * Ww];   // attn[h][w][k] (post-softmax)
__device__ float g_vsum[Cc * Hh * Ww];   // 7x7 box sum of vpad

// ---------------- kernel 0: zero the 3-wide halo of padded buffers ---------
__global__ void k_zero() {
    const int n = Cc * HPWP;
    for (int i = blockIdx.x * blockDim.x + threadIdx.x; i < n;
         i += gridDim.x * blockDim.x) {
        const int rw = i % HPWP;
        const int r = rw / WP, w = rw % WP;
        if (r < PAD || r >= HP - PAD || w < PAD || w >= WP - PAD) {
            g_qpad[i] = 0.f; g_kpad[i] = 0.f; g_vpad[i] = 0.f;
        }
    }
}

// ---------------- kernel 1: q/k/v = 1x1 conv (f32x2 packed) ----------------
// grid 512, block 256. Each warp: 32 consecutive pixels, 8 output channels.
// W transposed in smem (stride 66) so output-channel pairs are adjacent.
__global__ void k_qkv(const float* __restrict__ x,
                      const float* __restrict__ Wq, const float* __restrict__ bq,
                      const float* __restrict__ Wk, const float* __restrict__ bk,
                      const float* __restrict__ Wv, const float* __restrict__ bv) {
    extern __shared__ float sW[];            // 3 * 64*66 floats = 50688 B
    float* sWq = sW;
    float* sWk = sW + Cc * 66;
    float* sWv = sW + 2 * Cc * 66;
    for (int i = threadIdx.x; i < Cc * Cc; i += blockDim.x) {
        const int o = i >> 6, c = i & 63;    // W[o][c] -> sWt[c][o]
        sWq[c * 66 + o] = Wq[i];
        sWk[c * 66 + o] = Wk[i];
        sWv[c * 66 + o] = Wv[i];
    }
    __syncthreads();

    const int base = blockIdx.x * 32;
    const int p    = threadIdx.x & 31;
    const int og   = (threadIdx.x >> 5) * 8;
    const int s    = base + p;
    const int h = s >> 7, w = s & 127;
    const int po = (h + PAD) * WP + (w + PAD);

    float xv[Cc];
#pragma unroll
    for (int c = 0; c < Cc; c++) xv[c] = x[c * (Hh * Ww) + s];

    unsigned long long aq[4], ak[4], av[4];
#pragma unroll
    for (int jj = 0; jj < 4; jj++) {
        aq[jj] = pkf2(*(const float2*)&bq[og + 2 * jj]);
        ak[jj] = pkf2(*(const float2*)&bk[og + 2 * jj]);
        av[jj] = pkf2(*(const float2*)&bv[og + 2 * jj]);
    }
#pragma unroll 4
    for (int c = 0; c < Cc; c++) {
        const unsigned long long xd = pk2(xv[c], xv[c]);
#pragma unroll
        for (int jj = 0; jj < 4; jj++) {
            aq[jj] = ffma2(pkf2(*(const float2*)&sWq[c * 66 + og + 2 * jj]), xd, aq[jj]);
            ak[jj] = ffma2(pkf2(*(const float2*)&sWk[c * 66 + og + 2 * jj]), xd, ak[jj]);
            av[jj] = ffma2(pkf2(*(const float2*)&sWv[c * 66 + og + 2 * jj]), xd, av[jj]);
        }
    }
#pragma unroll
    for (int jj = 0; jj < 4; jj++) {
        const int o = og + 2 * jj;
        const float2 q2 = upk(aq[jj]), k2 = upk(ak[jj]), v2 = upk(av[jj]);
        g_qpad[o * HPWP + po] = q2.x; g_qpad[(o + 1) * HPWP + po] = q2.y;
        g_kpad[o * HPWP + po] = k2.x; g_kpad[(o + 1) * HPWP + po] = k2.y;
        g_vpad[o * HPWP + po] = v2.x; g_vpad[(o + 1) * HPWP + po] = v2.y;
    }
}

// ---------------- kernel 2: per-row Gram matrix + diagonal 7-band sum ------
// grid = HP, block 256. Tiles: 16(w) x 16(k) of 9x10; k packed as 5 f32x2.
__global__ void __launch_bounds__(256, 1) k_gram() {
    extern __shared__ float sm[];
    float* sQ = sm;                      // [64][160]
    float* sK = sm + Cc * SST;           // [64][160]
    float* sS = sm + 2 * Cc * SST;       // [144][160]
    const int r = blockIdx.x;
    const int tid = threadIdx.x;

    for (int i = tid; i < Cc * SST; i += 256) {
        const int c = i / SST, w = i % SST;
        float qv = 0.f, kv = 0.f;
        if (w < WP) {
            qv = g_qpad[c * HPWP + r * WP + w];
            kv = g_kpad[c * HPWP + r * WP + w];
        }
        sQ[i] = qv; sK[i] = kv;
    }
    __syncthreads();

    {
        const int kt = tid & 15, wt = tid >> 4;
        const int k0 = kt * 10, w0 = wt * 9;
        unsigned long long acc[9][5];
#pragma unroll
        for (int i = 0; i < 9; i++)
#pragma unroll
            for (int j = 0; j < 5; j++) acc[i][j] = 0ull;

#pragma unroll 2
        for (int c = 0; c < Cc; c++) {
            unsigned long long q2[9], kk2[5];
#pragma unroll
            for (int i = 0; i < 9; i++) {
                const float qv = sQ[c * SST + w0 + i];
                q2[i] = pk2(qv, qv);
            }
#pragma unroll
            for (int j = 0; j < 5; j++)
                kk2[j] = pkf2(*(const float2*)&sK[c * SST + k0 + 2 * j]);
#pragma unroll
            for (int i = 0; i < 9; i++)
#pragma unroll
                for (int j = 0; j < 5; j++)
                    acc[i][j] = ffma2(q2[i], kk2[j], acc[i][j]);
        }
#pragma unroll
        for (int i = 0; i < 9; i++)
#pragma unroll
            for (int j = 0; j < 5; j++)
                *(float2*)&sS[(w0 + i) * SST + k0 + 2 * j] = upk(acc[i][j]);
    }
    __syncthreads();

    // T[w][k] = sum_{pj<7} S[w+pj][k+pj]
    for (int o = tid; o < Hh * Ww; o += 256) {
        const int w = o >> 7, k = o & 127;
        float s = 0.f;
#pragma unroll
        for (int p = 0; p < WS; p++) s += sS[(w + p) * SST + (k + p)];
        g_T[r * (Hh * Ww) + o] = s;
    }
}

// ---------------- kernel 3: logits + softmax, h-tiled for T reuse ----------
// grid = 128(w) x 16(h-tiles of 8), block 256 (8 warps = 8 h each).
// Stages the 14 shared T-rows once per block: 4x less L2 traffic.
__global__ void k_softmax() {
    __shared__ float sT[14 * 128];
    const int bid = blockIdx.x;
    const int w = bid & 127;
    const int h0 = (bid >> 7) * 8;
    const int tid = threadIdx.x;

    for (int i = tid; i < 14 * 32; i += 256) {
        const int rr = i >> 5, k4 = (i & 31) * 4;
        *(float4*)&sT[rr * 128 + k4] =
            *(const float4*)&g_T[(h0 + rr) * (Hh * Ww) + w * Ww + k4];
    }
    __syncthreads();

    const int ww = tid >> 5, lane = tid & 31;
    float4 lg = make_float4(0.f, 0.f, 0.f, 0.f);
#pragma unroll
    for (int p = 0; p < WS; p++) {
        const float4 t = *(const float4*)&sT[(ww + p) * 128 + lane * 4];
        lg.x += t.x; lg.y += t.y; lg.z += t.z; lg.w += t.w;
    }

    float m = fmaxf(fmaxf(lg.x, lg.y), fmaxf(lg.z, lg.w));
#pragma unroll
    for (int off = 16; off; off >>= 1)
        m = fmaxf(m, __shfl_xor_sync(0xffffffffu, m, off));

    float4 e;
    e.x = __expf(lg.x - m); e.y = __expf(lg.y - m);
    e.z = __expf(lg.z - m); e.w = __expf(lg.w - m);
    float s = e.x + e.y + e.z + e.w;
#pragma unroll
    for (int off = 16; off; off >>= 1)
        s += __shfl_xor_sync(0xffffffffu, s, off);

    const float inv = 1.0f / s;
    e.x *= inv; e.y *= inv; e.z *= inv; e.w *= inv;
    *(float4*)&g_attn[((h0 + ww) * Ww + w) * Ww + lane * 4] = e;
}

// ---------------- kernel 4: fused separable 7x7 box of vpad -> vsum --------
// grid = 64(c) x 8(h-tiles of 16), block 256, static smem 23.3 KB.
__global__ void k_box() {
    __shared__ float sv[22 * 136];
    __shared__ float hs[22 * 128];
    const int c = blockIdx.x >> 3;
    const int h0 = (blockIdx.x & 7) * 16;
    const int tid = threadIdx.x;

    for (int i = tid; i < 22 * WP; i += 256) {
        const int rr = i / WP, w = i % WP;
        sv[rr * 136 + w] = g_vpad[c * HPWP + (h0 + rr) * WP + w];
    }
    __syncthreads();
    for (int i = tid; i < 22 * 128; i += 256) {
        const int rr = i >> 7, k = i & 127;
        float s = 0.f;
#pragma unroll
        for (int p = 0; p < WS; p++) s += sv[rr * 136 + k + p];
        hs[i] = s;
    }
    __syncthreads();
    for (int i = tid; i < 16 * 128; i += 256) {
        const int hh = i >> 7, k = i & 127;
        float s = 0.f;
#pragma unroll
        for (int p = 0; p < WS; p++) s += hs[(hh + p) * 128 + k];
        g_vsum[(c * Hh + h0 + hh) * Ww + k] = s;
    }
}

// ---------------- kernel 5: out[c,h,w] = sum_k attn[h,w,k]*vsum[c,h,k] -----
// grid = H, block 256. f32x2 packed along c (vsum pairs adjacent in sV).
__global__ void k_out(float* __restrict__ out) {
    extern __shared__ float sm[];
    float* sA = sm;                 // attn transposed: [k][w], stride 129
    float* sV = sm + 128 * 129;     // vsum transposed: [k][c], stride 66
    const int h = blockIdx.x;
    const int tid = threadIdx.x;

    for (int i = tid; i < Hh * Ww; i += 256) {          // i = w*128 + k
        const int w = i >> 7, k = i & 127;
        sA[k * 129 + w] = g_attn[h * (Hh * Ww) + i];
    }
    for (int i = tid; i < Cc * Ww; i += 256) {
        const int c = i >> 7, k = i & 127;
        sV[k * 66 + c] = g_vsum[(c * Hh + h) * Ww + k];
    }
    __syncthreads();

    const int lane = tid & 31;
    const int c0 = (tid >> 5) * 8;          // warp's 8 channels (4 pairs)
    unsigned long long acc[4][4];
#pragma unroll
    for (int i = 0; i < 4; i++)
#pragma unroll
        for (int j = 0; j < 4; j++) acc[i][j] = 0ull;

#pragma unroll 2
    for (int k = 0; k < 128; k++) {
        unsigned long long vv[4], av[4];
#pragma unroll
        for (int i = 0; i < 4; i++)          // warp-uniform -> broadcast
            vv[i] = pkf2(*(const float2*)&sV[k * 66 + c0 + 2 * i]);
#pragma unroll
        for (int j = 0; j < 4; j++) {        // conflict-free (stride-129 rows)
            const float a = sA[k * 129 + lane + 32 * j];
            av[j] = pk2(a, a);
        }
#pragma unroll
        for (int i = 0; i < 4; i++)
#pragma unroll
            for (int j = 0; j < 4; j++)
                acc[i][j] = ffma2(vv[i], av[j], acc[i][j]);
    }
#pragma unroll
    for (int i = 0; i < 4; i++)
#pragma unroll
        for (int j = 0; j < 4; j++) {
            const float2 v = upk(acc[i][j]);
            out[(c0 + 2 * i)     * (Hh * Ww) + h * Ww + lane + 32 * j] = v.x;
            out[(c0 + 2 * i + 1) * (Hh * Ww) + h * Ww + lane + 32 * j] = v.y;
        }
}

// ---------------------------------------------------------------------------
extern "C" void kernel_launch(void* const* d_in, const int* in_sizes, int n_in,
                              void* d_out, int out_size) {
    const float* x  = (const float*)d_in[0];
    const float* Wq = (const float*)d_in[1];
    const float* bq = (const float*)d_in[2];
    const float* Wk = (const float*)d_in[3];
    const float* bk = (const float*)d_in[4];
    const float* Wv = (const float*)d_in[5];
    const float* bv = (const float*)d_in[6];
    float* out = (float*)d_out;

    const int smemQKV = 3 * Cc * 66 * 4;                 // 50688
    const int smemB   = (2 * Cc * SST + 144 * SST) * 4;  // 174080
    const int smemE   = (128 * 129 + 128 * 66) * 4;      // 99840
    cudaFuncSetAttribute(k_qkv,  cudaFuncAttributeMaxDynamicSharedMemorySize, smemQKV);
    cudaFuncSetAttribute(k_gram, cudaFuncAttributeMaxDynamicSharedMemorySize, smemB);
    cudaFuncSetAttribute(k_out,  cudaFuncAttributeMaxDynamicSharedMemorySize, smemE);

    k_zero<<<256, 256>>>();
    k_qkv<<<(Hh * Ww) / 32, 256, smemQKV>>>(x, Wq, bq, Wk, bk, Wv, bv);
    k_gram<<<HP, 256, smemB>>>();
    k_softmax<<<Hh * 16, 256>>>();
    k_box<<<Cc * 8, 256>>>();
    k_out<<<Hh, 256, smemE>>>(out);
}

// round 8
// speedup vs baseline: 1.1264x; 1.1264x over previous
#include <cuda_runtime.h>

#define Hh 128
#define Ww 128
#define Cc 64
#define PAD 3
#define HP 134
#define WP 134
#define WS 7
#define SST 160
#define HPWP (HP * WP)

// ---------------- scratch (device globals; no allocation allowed) ----------
__device__ float g_qpad[Cc * HPWP];      // padded q  (C, HP, WP)
__device__ float g_kpad[Cc * HPWP];
__device__ float g_vpad[Cc * HPWP];
__device__ float g_T[HP * Hh * Ww];      // T[r][w][k] = sum_pj S_r[w+pj, k+pj]
__device__ float g_attn[Hh * Ww * Ww];   // attn[h][w][k] (post-softmax)
__device__ float g_vsum[Cc * Hh * Ww];   // 7x7 box sum of vpad

// ---------------- kernel 0: zero ONLY the 3-wide halo, direct indexing -----
// Halo per channel: rows {0,1,2,131,132,133} full (804) + cols {0,1,2,131,
// 132,133} over interior rows 3..130 (768) = 1572 elements.
#define HALO_PER_C 1572
__global__ void k_zero() {
    const int t = blockIdx.x * blockDim.x + threadIdx.x;
    if (t >= Cc * HALO_PER_C) return;
    const int c = t / HALO_PER_C;
    const int e = t - c * HALO_PER_C;
    int row, w;
    if (e < 804) {
        const int r6 = e / 134;
        w = e - r6 * 134;
        row = (r6 < 3) ? r6 : r6 + 128;         // 0,1,2,131,132,133
    } else {
        const int f = e - 804;
        const int q = f >> 7;                   // 0..5
        w = (q < 3) ? q : q + 128;              // 0,1,2,131,132,133
        row = (f & 127) + 3;                    // 3..130
    }
    const int idx = c * HPWP + row * WP + w;
    g_qpad[idx] = 0.f; g_kpad[idx] = 0.f; g_vpad[idx] = 0.f;
}

// ---------------- kernel 1: q/k/v = 1x1 conv ------------------------------
// grid 256, block 512 (16 warps -> 4/SMSP). Warp: 32 consecutive pixels
// (pixel-group = warp>>3), 8 output channels (o-group = warp&7).
__global__ void __launch_bounds__(512) k_qkv(
        const float* __restrict__ x,
        const float* __restrict__ Wq, const float* __restrict__ bq,
        const float* __restrict__ Wk, const float* __restrict__ bk,
        const float* __restrict__ Wv, const float* __restrict__ bv) {
    __shared__ float sW[3 * Cc * Cc];   // 48 KB
    float* sWq = sW;
    float* sWk = sW + Cc * Cc;
    float* sWv = sW + 2 * Cc * Cc;
    for (int i = threadIdx.x; i < Cc * Cc; i += 512) {
        sWq[i] = Wq[i]; sWk[i] = Wk[i]; sWv[i] = Wv[i];
    }
    __syncthreads();

    const int tid  = threadIdx.x;
    const int p    = tid & 31;
    const int warp = tid >> 5;
    const int og   = (warp & 7) * 8;
    const int pg   = (warp >> 3) * 32;
    const int s    = blockIdx.x * 64 + pg + p;
    const int h = s >> 7, w = s & 127;
    const int po = (h + PAD) * WP + (w + PAD);

    float xv[Cc];
#pragma unroll
    for (int c = 0; c < Cc; c++) xv[c] = x[c * (Hh * Ww) + s];

#pragma unroll
    for (int oo = 0; oo < 8; oo++) {
        const int o = og + oo;
        float aq = __ldg(&bq[o]), ak = __ldg(&bk[o]), av = __ldg(&bv[o]);
#pragma unroll
        for (int c = 0; c < Cc; c++) {
            const float xc = xv[c];
            aq += sWq[o * Cc + c] * xc;
            ak += sWk[o * Cc + c] * xc;
            av += sWv[o * Cc + c] * xc;
        }
        g_qpad[o * HPWP + po] = aq;
        g_kpad[o * HPWP + po] = ak;
        g_vpad[o * HPWP + po] = av;
    }
}

// ---------------- kernel 2: per-row Gram matrix + diagonal 7-band sum ------
// grid = HP, block 384 (12 warps -> 3/SMSP). 16(w) x 24(k) tiles of 9x6;
// all 384 threads active; FMA-pipe floor now reachable with 3 warps/SMSP.
__global__ void __launch_bounds__(384, 1) k_gram() {
    extern __shared__ float sm[];
    float* sQ = sm;                      // [64][160]
    float* sK = sm + Cc * SST;           // [64][160]
    float* sS = sm + 2 * Cc * SST;       // [144][160]
    const int r = blockIdx.x;
    const int tid = threadIdx.x;

    for (int i = tid; i < Cc * SST; i += 384) {
        const int c = i / SST, w = i - c * SST;
        float qv = 0.f, kv = 0.f;
        if (w < WP) {
            qv = g_qpad[c * HPWP + r * WP + w];
            kv = g_kpad[c * HPWP + r * WP + w];
        }
        sQ[i] = qv; sK[i] = kv;
    }
    __syncthreads();

    {
        const int kt = tid % 24, wt = tid / 24;   // 24 x 16 tile grid
        const int k0 = kt * 6, w0 = wt * 9;
        float acc[9][6];
#pragma unroll
        for (int i = 0; i < 9; i++)
#pragma unroll
            for (int j = 0; j < 6; j++) acc[i][j] = 0.f;

#pragma unroll 2
        for (int c = 0; c < Cc; c++) {
            float q[9], kk[6];
#pragma unroll
            for (int i = 0; i < 9; i++) q[i] = sQ[c * SST + w0 + i];
#pragma unroll
            for (int j = 0; j < 6; j++) kk[j] = sK[c * SST + k0 + j];
#pragma unroll
            for (int i = 0; i < 9; i++)
#pragma unroll
                for (int j = 0; j < 6; j++) acc[i][j] += q[i] * kk[j];
        }
#pragma unroll
        for (int i = 0; i < 9; i++)
#pragma unroll
            for (int j = 0; j < 6; j++)
                sS[(w0 + i) * SST + k0 + j] = acc[i][j];
    }
    __syncthreads();

    // T[w][k] = sum_{pj<7} S[w+pj][k+pj]
    for (int o = tid; o < Hh * Ww; o += 384) {
        const int w = o >> 7, k = o & 127;
        float s = 0.f;
#pragma unroll
        for (int p = 0; p < WS; p++) s += sS[(w + p) * SST + (k + p)];
        g_T[r * (Hh * Ww) + o] = s;
    }
}

// ---------------- kernel 3: logits = sum_pi T[h+pi], softmax over k --------
// One warp per (h,w); 4 k per lane via float4. grid 2048, block 256.
__global__ void k_softmax() {
    const int warp = (blockIdx.x * blockDim.x + threadIdx.x) >> 5;  // 0..16383
    const int lane = threadIdx.x & 31;
    const int h = warp >> 7, w = warp & 127;

    float4 lg = make_float4(0.f, 0.f, 0.f, 0.f);
#pragma unroll
    for (int p = 0; p < WS; p++) {
        const float4 t = *(const float4*)&g_T[(h + p) * (Hh * Ww) + w * Ww + lane * 4];
        lg.x += t.x; lg.y += t.y; lg.z += t.z; lg.w += t.w;
    }

    float m = fmaxf(fmaxf(lg.x, lg.y), fmaxf(lg.z, lg.w));
#pragma unroll
    for (int off = 16; off; off >>= 1)
        m = fmaxf(m, __shfl_xor_sync(0xffffffffu, m, off));

    float4 e;
    e.x = __expf(lg.x - m); e.y = __expf(lg.y - m);
    e.z = __expf(lg.z - m); e.w = __expf(lg.w - m);
    float s = e.x + e.y + e.z + e.w;
#pragma unroll
    for (int off = 16; off; off >>= 1)
        s += __shfl_xor_sync(0xffffffffu, s, off);

    const float inv = 1.0f / s;
    e.x *= inv; e.y *= inv; e.z *= inv; e.w *= inv;
    *(float4*)&g_attn[warp * Ww + lane * 4] = e;
}

// ---------------- kernel 4: fused separable 7x7 box of vpad -> vsum --------
// grid = 64(c) x 8(h-tiles of 16), block 256, static smem 23.3 KB.
__global__ void k_box() {
    __shared__ float sv[22 * 136];
    __shared__ float hs[22 * 128];
    const int c = blockIdx.x >> 3;
    const int h0 = (blockIdx.x & 7) * 16;
    const int tid = threadIdx.x;

    for (int i = tid; i < 22 * WP; i += 256) {
        const int rr = i / WP, w = i - rr * WP;
        sv[rr * 136 + w] = g_vpad[c * HPWP + (h0 + rr) * WP + w];
    }
    __syncthreads();
    for (int i = tid; i < 22 * 128; i += 256) {
        const int rr = i >> 7, k = i & 127;
        float s = 0.f;
#pragma unroll
        for (int p = 0; p < WS; p++) s += sv[rr * 136 + k + p];
        hs[i] = s;
    }
    __syncthreads();
    for (int i = tid; i < 16 * 128; i += 256) {
        const int hh = i >> 7, k = i & 127;
        float s = 0.f;
#pragma unroll
        for (int p = 0; p < WS; p++) s += hs[(hh + p) * 128 + k];
        g_vsum[(c * Hh + h0 + hh) * Ww + k] = s;
    }
}

// ---------------- kernel 5: out[c,h,w] = sum_k attn[h,w,k]*vsum[c,h,k] -----
// grid = H, block 512 (16 warps -> 4/SMSP). Warp ww owns 4 channels
// (broadcast sV reads); lane l owns w in {l,l+32,l+64,l+96} (conflict-free).
__global__ void __launch_bounds__(512) k_out(float* __restrict__ out) {
    extern __shared__ float sm[];
    float* sA = sm;                 // attn transposed: [k][w], stride 129
    float* sV = sm + 128 * 129;     // vsum transposed: [k][c], stride 66
    const int h = blockIdx.x;
    const int tid = threadIdx.x;

    for (int i = tid; i < Hh * Ww; i += 512) {          // i = w*128 + k
        const int w = i >> 7, k = i & 127;
        sA[k * 129 + w] = g_attn[h * (Hh * Ww) + i];
    }
    for (int i = tid; i < Cc * Ww; i += 512) {
        const int c = i >> 7, k = i & 127;
        sV[k * 66 + c] = g_vsum[(c * Hh + h) * Ww + k];
    }
    __syncthreads();

    const int lane = tid & 31;
    const int c0 = (tid >> 5) * 4;          // warp's 4 channels
    float acc[4][4];
#pragma unroll
    for (int i = 0; i < 4; i++)
#pragma unroll
        for (int j = 0; j < 4; j++) acc[i][j] = 0.f;

#pragma unroll 2
    for (int k = 0; k < 128; k++) {
        float av[4], vv[4];
#pragma unroll
        for (int j = 0; j < 4; j++) av[j] = sA[k * 129 + lane + 32 * j];
#pragma unroll
        for (int i = 0; i < 4; i++) vv[i] = sV[k * 66 + c0 + i];  // broadcast
#pragma unroll
        for (int i = 0; i < 4; i++)
#pragma unroll
            for (int j = 0; j < 4; j++) acc[i][j] += vv[i] * av[j];
    }
#pragma unroll
    for (int i = 0; i < 4; i++)
#pragma unroll
        for (int j = 0; j < 4; j++)
            out[(c0 + i) * (Hh * Ww) + h * Ww + lane + 32 * j] = acc[i][j];
}

// ---------------------------------------------------------------------------
extern "C" void kernel_launch(void* const* d_in, const int* in_sizes, int n_in,
                              void* d_out, int out_size) {
    const float* x  = (const float*)d_in[0];
    const float* Wq = (const float*)d_in[1];
    const float* bq = (const float*)d_in[2];
    const float* Wk = (const float*)d_in[3];
    const float* bk = (const float*)d_in[4];
    const float* Wv = (const float*)d_in[5];
    const float* bv = (const float*)d_in[6];
    float* out = (float*)d_out;

    const int smemB = (2 * Cc * SST + 144 * SST) * 4;   // 174080
    const int smemE = (128 * 129 + 128 * 66) * 4;       // 99840
    cudaFuncSetAttribute(k_gram, cudaFuncAttributeMaxDynamicSharedMemorySize, smemB);
    cudaFuncSetAttribute(k_out,  cudaFuncAttributeMaxDynamicSharedMemorySize, smemE);

    k_zero<<<(Cc * HALO_PER_C + 255) / 256, 256>>>();
    k_qkv<<<(Hh * Ww) / 64, 512>>>(x, Wq, bq, Wk, bk, Wv, bv);
    k_gram<<<HP, 384, smemB>>>();
    k_softmax<<<(Hh * Ww) / 8, 256>>>();
    k_box<<<Cc * 8, 256>>>();
    k_out<<<Hh, 512, smemE>>>(out);
}

// round 16
// speedup vs baseline: 1.1852x; 1.0522x over previous
#include <cuda_runtime.h>

#define Hh 128
#define Ww 128
#define Cc 64
#define PAD 3
#define HP 134
#define WP 134
#define WS 7
#define SST 160
#define HPWP (HP * WP)

// ---------------- scratch (device globals; no allocation allowed) ----------
__device__ float g_qpad[Cc * HPWP];      // padded q  (C, HP, WP)
__device__ float g_kpad[Cc * HPWP];
__device__ float g_vpad[Cc * HPWP];
__device__ float g_T[HP * Hh * Ww];      // T[r][w][k] = sum_pj S_r[w+pj, k+pj]
__device__ float g_vsum[Cc * Hh * Ww];   // 7x7 box sum of vpad

#define HALO_PER_C 1572

// ---------------- kernel 1: halo-zero + q/k/v 1x1 conv --------------------
// grid 256, block 512 (16 warps -> 4/SMSP). Prologue: each thread zeroes one
// halo element (disjoint from the interior this kernel writes -> no race).
// Main: warp handles 32 consecutive pixels x 8 output channels.
__global__ void __launch_bounds__(512) k_qkv(
        const float* __restrict__ x,
        const float* __restrict__ Wq, const float* __restrict__ bq,
        const float* __restrict__ Wk, const float* __restrict__ bk,
        const float* __restrict__ Wv, const float* __restrict__ bv) {
    // ---- fused halo zeroing (body identical to the audited k_zero) ----
    {
        const int t = blockIdx.x * 512 + threadIdx.x;   // 131072 >= 100608
        if (t < Cc * HALO_PER_C) {
            const int c = t / HALO_PER_C;
            const int e = t - c * HALO_PER_C;
            int row, w;
            if (e < 804) {
                const int r6 = e / 134;
                w = e - r6 * 134;
                row = (r6 < 3) ? r6 : r6 + 128;         // 0,1,2,131,132,133
            } else {
                const int f = e - 804;
                const int q = f >> 7;                   // 0..5
                w = (q < 3) ? q : q + 128;              // 0,1,2,131,132,133
                row = (f & 127) + 3;                    // 3..130
            }
            const int idx = c * HPWP + row * WP + w;
            g_qpad[idx] = 0.f; g_kpad[idx] = 0.f; g_vpad[idx] = 0.f;
        }
    }

    __shared__ float sW[3 * Cc * Cc];   // 48 KB
    float* sWq = sW;
    float* sWk = sW + Cc * Cc;
    float* sWv = sW + 2 * Cc * Cc;
    for (int i = threadIdx.x; i < Cc * Cc; i += 512) {
        sWq[i] = Wq[i]; sWk[i] = Wk[i]; sWv[i] = Wv[i];
    }
    __syncthreads();

    const int tid  = threadIdx.x;
    const int p    = tid & 31;
    const int warp = tid >> 5;
    const int og   = (warp & 7) * 8;
    const int pg   = (warp >> 3) * 32;
    const int s    = blockIdx.x * 64 + pg + p;
    const int h = s >> 7, w = s & 127;
    const int po = (h + PAD) * WP + (w + PAD);

    float xv[Cc];
#pragma unroll
    for (int c = 0; c < Cc; c++) xv[c] = x[c * (Hh * Ww) + s];

#pragma unroll
    for (int oo = 0; oo < 8; oo++) {
        const int o = og + oo;
        float aq = __ldg(&bq[o]), ak = __ldg(&bk[o]), av = __ldg(&bv[o]);
#pragma unroll
        for (int c = 0; c < Cc; c++) {
            const float xc = xv[c];
            aq += sWq[o * Cc + c] * xc;
            ak += sWk[o * Cc + c] * xc;
            av += sWv[o * Cc + c] * xc;
        }
        g_qpad[o * HPWP + po] = aq;
        g_kpad[o * HPWP + po] = ak;
        g_vpad[o * HPWP + po] = av;
    }
}

// ---------------- kernel 2: fused separable 7x7 box of vpad -> vsum --------
__global__ void k_box() {
    __shared__ float sv[22 * 136];
    __shared__ float hs[22 * 128];
    const int c = blockIdx.x >> 3;
    const int h0 = (blockIdx.x & 7) * 16;
    const int tid = threadIdx.x;

    for (int i = tid; i < 22 * WP; i += 256) {
        const int rr = i / WP, w = i - rr * WP;
        sv[rr * 136 + w] = g_vpad[c * HPWP + (h0 + rr) * WP + w];
    }
    __syncthreads();
    for (int i = tid; i < 22 * 128; i += 256) {
        const int rr = i >> 7, k = i & 127;
        float s = 0.f;
#pragma unroll
        for (int p = 0; p < WS; p++) s += sv[rr * 136 + k + p];
        hs[i] = s;
    }
    __syncthreads();
    for (int i = tid; i < 16 * 128; i += 256) {
        const int hh = i >> 7, k = i & 127;
        float s = 0.f;
#pragma unroll
        for (int p = 0; p < WS; p++) s += hs[(hh + p) * 128 + k];
        g_vsum[(c * Hh + h0 + hh) * Ww + k] = s;
    }
}

// ---------------- kernel 3: per-row Gram matrix + diagonal 7-band sum ------
// grid = HP, block 384 (12 warps -> 3/SMSP). 16(w) x 24(k) tiles of 9x6.
__global__ void __launch_bounds__(384, 1) k_gram() {
    extern __shared__ float sm[];
    float* sQ = sm;                      // [64][160]
    float* sK = sm + Cc * SST;           // [64][160]
    float* sS = sm + 2 * Cc * SST;       // [144][160]
    const int r = blockIdx.x;
    const int tid = threadIdx.x;

    for (int i = tid; i < Cc * SST; i += 384) {
        const int c = i / SST, w = i - c * SST;
        float qv = 0.f, kv = 0.f;
        if (w < WP) {
            qv = g_qpad[c * HPWP + r * WP + w];
            kv = g_kpad[c * HPWP + r * WP + w];
        }
        sQ[i] = qv; sK[i] = kv;
    }
    __syncthreads();

    {
        const int kt = tid % 24, wt = tid / 24;   // 24 x 16 tile grid
        const int k0 = kt * 6, w0 = wt * 9;
        float acc[9][6];
#pragma unroll
        for (int i = 0; i < 9; i++)
#pragma unroll
            for (int j = 0; j < 6; j++) acc[i][j] = 0.f;

#pragma unroll 2
        for (int c = 0; c < Cc; c++) {
            float q[9], kk[6];
#pragma unroll
            for (int i = 0; i < 9; i++) q[i] = sQ[c * SST + w0 + i];
#pragma unroll
            for (int j = 0; j < 6; j++) kk[j] = sK[c * SST + k0 + j];
#pragma unroll
            for (int i = 0; i < 9; i++)
#pragma unroll
                for (int j = 0; j < 6; j++) acc[i][j] += q[i] * kk[j];
        }
#pragma unroll
        for (int i = 0; i < 9; i++)
#pragma unroll
            for (int j = 0; j < 6; j++)
                sS[(w0 + i) * SST + k0 + j] = acc[i][j];
    }
    __syncthreads();

    // T[w][k] = sum_{pj<7} S[w+pj][k+pj]
    for (int o = tid; o < Hh * Ww; o += 384) {
        const int w = o >> 7, k = o & 127;
        float s = 0.f;
#pragma unroll
        for (int p = 0; p < WS; p++) s += sS[(w + p) * SST + (k + p)];
        g_T[r * (Hh * Ww) + o] = s;
    }
}

// ---------------- kernel 4: FUSED logits + softmax + attn@vsum GEMM --------
// grid = H (one CTA per h), block 512, dyn smem 101376 B.
__global__ void __launch_bounds__(512) k_out(float* __restrict__ out) {
    extern __shared__ float sm[];
    float* sL = sm;                 // [128(w)][132]  logits -> attn
    float* sV = sm + 128 * 132;     // [128(k)][66]   vsum transposed
    const int h = blockIdx.x;
    const int tid = threadIdx.x;
    const int lane = tid & 31;
    const int ww = tid >> 5;        // 0..15

    // stage sV[k][c]
    for (int i = tid; i < Cc * Ww; i += 512) {
        const int c = i >> 7, k = i & 127;
        sV[k * 66 + c] = g_vsum[(c * Hh + h) * Ww + k];
    }
    // phase 1: vertical 7-sum of T -> sL (i indexes float4 over 16384)
    for (int i = tid; i < 4096; i += 512) {
        const int w = i >> 5, k4 = (i & 31) * 4;     // i*4 == w*128+k4
        float4 a = *(const float4*)&g_T[h * (Hh * Ww) + i * 4];
#pragma unroll
        for (int p = 1; p < WS; p++) {
            const float4 t = *(const float4*)&g_T[(h + p) * (Hh * Ww) + i * 4];
            a.x += t.x; a.y += t.y; a.z += t.z; a.w += t.w;
        }
        *(float4*)&sL[w * 132 + k4] = a;
    }
    __syncthreads();

    // phase 2: softmax over k for each row w (warp per row, 8 rows/warp)
#pragma unroll
    for (int rr = 0; rr < 8; rr++) {
        const int w = ww * 8 + rr;
        float4 v = *(float4*)&sL[w * 132 + 4 * lane];
        float m = fmaxf(fmaxf(v.x, v.y), fmaxf(v.z, v.w));
#pragma unroll
        for (int off = 16; off; off >>= 1)
            m = fmaxf(m, __shfl_xor_sync(0xffffffffu, m, off));
        float4 e;
        e.x = __expf(v.x - m); e.y = __expf(v.y - m);
        e.z = __expf(v.z - m); e.w = __expf(v.w - m);
        float s = e.x + e.y + e.z + e.w;
#pragma unroll
        for (int off = 16; off; off >>= 1)
            s += __shfl_xor_sync(0xffffffffu, s, off);
        const float inv = 1.0f / s;
        e.x *= inv; e.y *= inv; e.z *= inv; e.w *= inv;
        *(float4*)&sL[w * 132 + 4 * lane] = e;
    }
    __syncthreads();

    // phase 3: GEMM. Warp ww owns 4 channels c0..c0+3; lane l owns
    // w in {l, l+32, l+64, l+96}. k skewed per-lane for bank freedom.
    const int c0 = ww * 4;
    float acc[4][4];
#pragma unroll
    for (int i = 0; i < 4; i++)
#pragma unroll
        for (int j = 0; j < 4; j++) acc[i][j] = 0.f;

#pragma unroll 2
    for (int t = 0; t < 128; t++) {
        const int kk = (t + lane) & 127;
        float vv[4], av[4];
#pragma unroll
        for (int i = 0; i < 4; i++) vv[i] = sV[kk * 66 + c0 + i];     // 2-way
#pragma unroll
        for (int j = 0; j < 4; j++) av[j] = sL[(lane + 32 * j) * 132 + kk]; // cf
#pragma unroll
        for (int i = 0; i < 4; i++)
#pragma unroll
            for (int j = 0; j < 4; j++) acc[i][j] += vv[i] * av[j];
    }
#pragma unroll
    for (int i = 0; i < 4; i++)
#pragma unroll
        for (int j = 0; j < 4; j++)
            out[(c0 + i) * (Hh * Ww) + h * Ww + lane + 32 * j] = acc[i][j];
}

// ---------------------------------------------------------------------------
extern "C" void kernel_launch(void* const* d_in, const int* in_sizes, int n_in,
                              void* d_out, int out_size) {
    const float* x  = (const float*)d_in[0];
    const float* Wq = (const float*)d_in[1];
    const float* bq = (const float*)d_in[2];
    const float* Wk = (const float*)d_in[3];
    const float* bk = (const float*)d_in[4];
    const float* Wv = (const float*)d_in[5];
    const float* bv = (const float*)d_in[6];
    float* out = (float*)d_out;

    const int smemB = (2 * Cc * SST + 144 * SST) * 4;   // 174080
    const int smemE = (128 * 132 + 128 * 66) * 4;       // 101376
    cudaFuncSetAttribute(k_gram, cudaFuncAttributeMaxDynamicSharedMemorySize, smemB);
    cudaFuncSetAttribute(k_out,  cudaFuncAttributeMaxDynamicSharedMemorySize, smemE);

    k_qkv<<<(Hh * Ww) / 64, 512>>>(x, Wq, bq, Wk, bk, Wv, bv); // #1 (+halo zero)
    k_box<<<Cc * 8, 256>>>();                             // #2
    k_gram<<<HP, 384, smemB>>>();                         // #3
    k_out<<<Hh, 512, smemE>>>(out);                       // #4 <- likely ncu slot
}